// round 10
// baseline (speedup 1.0000x reference)
#include <cuda_runtime.h>
#include <cuda_bf16.h>
#include <cuda_fp16.h>
#include <cuda_fp8.h>
#include <cstdint>

#define B_ 65536
#define D_ 512
#define K_ 1024
#define C_ 100
#define TAU 16.0f

// ---------------- scratch (device globals; no allocations allowed) ----------------
__device__ __align__(16) uint8_t   g_Xf8[(size_t)B_ * D_];   // 32MB  X e4m3
__device__ __align__(16) uint8_t   g_Wf8[(size_t)K_ * D_];   // 512KB W^T e4m3
__device__ __align__(16) float     g_Wtf[(size_t)K_ * D_];   // 2MB   W^T fp32
__device__ __align__(16) uint32_t  g_cand[(size_t)B_ * 64];  // 16MB  (half<<16|k) candidates
__device__ float g_xsq[B_];
__device__ float g_wsq[K_];
__device__ int   g_assign[B_];
__device__ int   g_counts[K_];
__device__ int   g_offsets[K_];
__device__ int   g_cursor[K_];
__device__ int   g_order[B_];
__device__ float g_es[(size_t)K_ * D_];
__device__ int   g_bhist[K_ * C_];
__device__ float g_csnorm[K_];

__device__ __forceinline__ float GAM()  { return (float)0.99; }
__device__ __forceinline__ float OMG()  { return (float)(1.0 - 0.99); }
__device__ __forceinline__ float KEPS() { return (float)(1024 * 1e-5); }

// ---------------- PTX helpers (sm_89-era ISA; no tcgen05) ----------------
__device__ __forceinline__ uint32_t smem_u32(const void* p) {
    uint32_t a;
    asm("{ .reg .u64 t; cvta.to.shared.u64 t, %1; cvt.u32.u64 %0, t; }" : "=r"(a) : "l"(p));
    return a;
}
__device__ __forceinline__ void cp16(uint32_t s, const void* g) {
    asm volatile("cp.async.cg.shared.global [%0], [%1], 16;" :: "r"(s), "l"(g) : "memory");
}
#define CP_COMMIT() asm volatile("cp.async.commit_group;" ::: "memory")
#define CP_WAIT1()  asm volatile("cp.async.wait_group 1;" ::: "memory")
#define CP_WAIT0()  asm volatile("cp.async.wait_group 0;" ::: "memory")

__device__ __forceinline__ void ldm_x4(uint32_t& r0, uint32_t& r1, uint32_t& r2, uint32_t& r3, uint32_t a) {
    asm volatile("ldmatrix.sync.aligned.m8n8.x4.shared.b16 {%0,%1,%2,%3}, [%4];"
                 : "=r"(r0), "=r"(r1), "=r"(r2), "=r"(r3) : "r"(a));
}
__device__ __forceinline__ void mma16832(float* c, const uint32_t* a, const uint32_t* b) {
    asm volatile("mma.sync.aligned.m16n8k32.row.col.f32.e4m3.e4m3.f32 "
                 "{%0,%1,%2,%3}, {%4,%5,%6,%7}, {%8,%9}, {%0,%1,%2,%3};"
                 : "+f"(c[0]), "+f"(c[1]), "+f"(c[2]), "+f"(c[3])
                 : "r"(a[0]), "r"(a[1]), "r"(a[2]), "r"(a[3]), "r"(b[0]), "r"(b[1]));
}

// ---------------- init scratch ----------------
__global__ void k_init() {
    int i = blockIdx.x * blockDim.x + threadIdx.x;
    if (i < K_) { g_counts[i] = 0; g_wsq[i] = 0.f; }
    if (i < K_ * C_) g_bhist[i] = 0;
}

// ---------------- W transpose + wsq partials (grid 4 x 32) ----------------
__global__ void k_wt(const float* __restrict__ W) {
    __shared__ float tile[32][33];
    __shared__ float red[32][33];
    int k0 = blockIdx.y * 32;
    int dbase = blockIdx.x * 128;
    int tx = threadIdx.x, ty = threadIdx.y;

    float sq = 0.f;
    #pragma unroll
    for (int dt = 0; dt < 4; ++dt) {
        int d0 = dbase + dt * 32;
        float v = W[(size_t)(d0 + ty) * K_ + k0 + tx];
        tile[ty][tx] = v;
        sq += v * v;
        __syncthreads();
        float u = tile[tx][ty];
        g_Wtf[(size_t)(k0 + ty) * D_ + d0 + tx] = u;
        g_Wf8[(size_t)(k0 + ty) * D_ + d0 + tx] =
            (uint8_t)__nv_cvt_float_to_fp8(u, __NV_SATFINITE, __NV_E4M3);
        __syncthreads();
    }
    red[ty][tx] = sq;
    __syncthreads();
    #pragma unroll
    for (int o = 16; o; o >>= 1) {
        if (ty < o) red[ty][tx] += red[ty + o][tx];
        __syncthreads();
    }
    if (ty == 0) atomicAdd(&g_wsq[k0 + tx], red[0][tx]);
}

// ---------------- X -> e4m3 + ||x||^2 (warp per row) ----------------
__global__ void k_xconv(const float* __restrict__ X) {
    int w = (blockIdx.x * blockDim.x + threadIdx.x) >> 5;
    int lane = threadIdx.x & 31;
    if (w >= B_) return;
    const float4* p = (const float4*)(X + (size_t)w * D_);
    uint32_t* dst = (uint32_t*)(g_Xf8 + (size_t)w * D_);
    float s = 0.f;
    #pragma unroll
    for (int j = 0; j < 4; ++j) {
        float4 v = p[lane + j * 32];
        s += v.x * v.x + v.y * v.y + v.z * v.z + v.w * v.w;
        __nv_fp8x2_storage_t lo = __nv_cvt_float2_to_fp8x2(make_float2(v.x, v.y), __NV_SATFINITE, __NV_E4M3);
        __nv_fp8x2_storage_t hi = __nv_cvt_float2_to_fp8x2(make_float2(v.z, v.w), __NV_SATFINITE, __NV_E4M3);
        dst[lane + j * 32] = (uint32_t)lo | ((uint32_t)hi << 16);
    }
    #pragma unroll
    for (int o = 16; o; o >>= 1) s += __shfl_xor_sync(0xFFFFFFFFu, s, o);
    if (lane == 0) g_xsq[w] = s;
}

// ---------------- fused fp8 GEMM + argmin: block owns 128 rows x all K ----------------
#define PITCH 144
#define BCHUNK 18432   // B chunk: 128 rows * 144B

__global__ void __launch_bounds__(256, 2)
k_gemm_argmin(const float* __restrict__ X, const int* __restrict__ keys,
              float* __restrict__ out_am) {
    extern __shared__ char dynsmem[];
    __shared__ float    xsq_s[128];
    __shared__ float    wsq_s[128];
    __shared__ uint32_t s_rowmin[128];
    __shared__ int      s_cnt[128];

    const int tid  = threadIdx.x;
    const int bm   = blockIdx.x;
    const int wid  = tid >> 5, lane = tid & 31;
    const int wm   = wid & 1;      // 2 warp-slots along M (64 rows each)
    const int wn   = wid >> 1;     // 4 warp-slots along N (32 cols each)

    uint32_t sbase = smem_u32(dynsmem);
    const uint32_t Asm = sbase;                                  // 64KB, swizzled flat
    const uint32_t Bbuf[2] = { sbase + 65536, sbase + 65536 + BCHUNK };

    if (tid < 128) {
        xsq_s[tid]    = g_xsq[bm * 128 + tid];
        s_rowmin[tid] = 0xFFFFFFFFu;
        s_cnt[tid]    = 0;
    }

    // ---- A resident load: 128 rows x 512B, unit u (16B) stored at u^(r&7)
    {
        const uint8_t* gA = g_Xf8 + (size_t)bm * 128 * D_;
        #pragma unroll
        for (int j = 0; j < 16; ++j) {
            int gidx = j * 256 + tid;
            int r = gidx >> 5, u = gidx & 31;
            cp16(Asm + r * 512 + ((uint32_t)(u ^ (r & 7)) << 4), gA + r * 512 + u * 16);
        }
    }
    // ---- B chunk issue: t = bn*4 + kt
    const int rB = tid >> 3, cB = tid & 7;
    const uint32_t sOffB = (uint32_t)(rB * PITCH + cB * 16);
    auto issueB = [&](int t, int bf) {
        int bn = t >> 2, kt = t & 3;
        const uint8_t* gB = g_Wf8 + (size_t)(bn * 128 + rB) * D_ + kt * 128 + cB * 16;
        #pragma unroll
        for (int i = 0; i < 4; ++i)
            cp16(Bbuf[bf] + sOffB + i * 32 * PITCH, gB + (size_t)i * 32 * D_);
    };

    issueB(0, 0); CP_COMMIT();     // group0 = A + B(0)
    issueB(1, 1); CP_COMMIT();     // group1 = B(1)

    // ldmatrix bases
    uint32_t aAddrBase[4], aSw[4];
    #pragma unroll
    for (int mt = 0; mt < 4; ++mt) {
        int rA = wm * 64 + mt * 16 + (lane & 15);
        aAddrBase[mt] = Asm + rA * 512;
        aSw[mt] = (uint32_t)(rA & 7);
    }
    const uint32_t uHalf = (uint32_t)(lane >> 4);
    uint32_t baseB_[2];
    #pragma unroll
    for (int np = 0; np < 2; ++np)
        baseB_[np] = (uint32_t)((wn * 32 + np * 16 + (lane & 7) + ((lane >> 4) << 3)) * PITCH
                                + (((lane >> 3) & 1) << 4));

    const int g = lane >> 2, th2 = (lane & 3) * 2;
    float acc[4][4][4];

    #pragma unroll 1
    for (int t = 0; t < 32; ++t) {
        const int bn = t >> 2, kt = t & 3;
        if (kt == 0) {
            #pragma unroll
            for (int a = 0; a < 4; ++a)
                #pragma unroll
                for (int b = 0; b < 4; ++b)
                    #pragma unroll
                    for (int q = 0; q < 4; ++q) acc[a][b][q] = 0.f;
        }
        if (t < 30) CP_WAIT1(); else CP_WAIT0();
        __syncthreads();
        const uint32_t Bb = Bbuf[t & 1];

        #pragma unroll
        for (int ks = 0; ks < 4; ++ks) {
            uint32_t a[4][4];
            #pragma unroll
            for (int mt = 0; mt < 4; ++mt) {
                uint32_t u = (uint32_t)(kt * 8 + ks * 2) + uHalf;
                ldm_x4(a[mt][0], a[mt][1], a[mt][2], a[mt][3],
                       aAddrBase[mt] + ((u ^ aSw[mt]) << 4));
            }
            uint32_t b[4][2];
            #pragma unroll
            for (int np = 0; np < 2; ++np)
                ldm_x4(b[2 * np][0], b[2 * np][1], b[2 * np + 1][0], b[2 * np + 1][1],
                       Bb + baseB_[np] + ks * 32);
            #pragma unroll
            for (int mt = 0; mt < 4; ++mt)
                #pragma unroll
                for (int nt = 0; nt < 4; ++nt)
                    mma16832(acc[mt][nt], a[mt], b[nt]);
        }
        __syncthreads();
        if (t + 2 < 32) { issueB(t + 2, t & 1); CP_COMMIT(); }

        if (kt == 3) {
            // tile epilogue: running row-min + candidate logging
            if (tid < 128) wsq_s[tid] = g_wsq[bn * 128 + tid];
            __syncthreads();
            // pass1: row mins (packed (half<<16)|k)
            #pragma unroll
            for (int mt = 0; mt < 4; ++mt) {
                int r0 = wm * 64 + mt * 16 + g;
                float xs0 = xsq_s[r0], xs1 = xsq_s[r0 + 8];
                uint32_t m0 = 0xFFFFFFFFu, m1 = 0xFFFFFFFFu;
                #pragma unroll
                for (int nt = 0; nt < 4; ++nt) {
                    int c = wn * 32 + nt * 8 + th2;
                    int kk = bn * 128 + c;
                    float w0 = wsq_s[c], w1 = wsq_s[c + 1];
                    uint32_t p;
                    p = ((uint32_t)__half_as_ushort(__float2half_rn(fmaxf((xs0 - 2.f * acc[mt][nt][0]) + w0, 0.f))) << 16) | (uint32_t)kk;
                    m0 = min(m0, p);
                    p = ((uint32_t)__half_as_ushort(__float2half_rn(fmaxf((xs0 - 2.f * acc[mt][nt][1]) + w1, 0.f))) << 16) | (uint32_t)(kk + 1);
                    m0 = min(m0, p);
                    p = ((uint32_t)__half_as_ushort(__float2half_rn(fmaxf((xs1 - 2.f * acc[mt][nt][2]) + w0, 0.f))) << 16) | (uint32_t)kk;
                    m1 = min(m1, p);
                    p = ((uint32_t)__half_as_ushort(__float2half_rn(fmaxf((xs1 - 2.f * acc[mt][nt][3]) + w1, 0.f))) << 16) | (uint32_t)(kk + 1);
                    m1 = min(m1, p);
                }
                atomicMin(&s_rowmin[r0], m0);
                atomicMin(&s_rowmin[r0 + 8], m1);
            }
            __syncthreads();
            // pass2: append candidates <= running_min + TAU (superset of final set)
            #pragma unroll
            for (int mt = 0; mt < 4; ++mt) {
                int r0 = wm * 64 + mt * 16 + g;
                float xs0 = xsq_s[r0], xs1 = xsq_s[r0 + 8];
                float t0 = __half2float(__ushort_as_half((unsigned short)(s_rowmin[r0] >> 16))) + TAU;
                float t1 = __half2float(__ushort_as_half((unsigned short)(s_rowmin[r0 + 8] >> 16))) + TAU;
                #pragma unroll
                for (int nt = 0; nt < 4; ++nt) {
                    int c = wn * 32 + nt * 8 + th2;
                    int kk = bn * 128 + c;
                    float w0 = wsq_s[c], w1 = wsq_s[c + 1];
                    __half h;
                    h = __float2half_rn(fmaxf((xs0 - 2.f * acc[mt][nt][0]) + w0, 0.f));
                    if (__half2float(h) <= t0) { int pos = atomicAdd(&s_cnt[r0], 1); if (pos < 64)
                        g_cand[((size_t)(bm * 128 + r0)) * 64 + pos] = ((uint32_t)__half_as_ushort(h) << 16) | (uint32_t)kk; }
                    h = __float2half_rn(fmaxf((xs0 - 2.f * acc[mt][nt][1]) + w1, 0.f));
                    if (__half2float(h) <= t0) { int pos = atomicAdd(&s_cnt[r0], 1); if (pos < 64)
                        g_cand[((size_t)(bm * 128 + r0)) * 64 + pos] = ((uint32_t)__half_as_ushort(h) << 16) | (uint32_t)(kk + 1); }
                    h = __float2half_rn(fmaxf((xs1 - 2.f * acc[mt][nt][2]) + w0, 0.f));
                    if (__half2float(h) <= t1) { int pos = atomicAdd(&s_cnt[r0 + 8], 1); if (pos < 64)
                        g_cand[((size_t)(bm * 128 + r0 + 8)) * 64 + pos] = ((uint32_t)__half_as_ushort(h) << 16) | (uint32_t)kk; }
                    h = __float2half_rn(fmaxf((xs1 - 2.f * acc[mt][nt][3]) + w1, 0.f));
                    if (__half2float(h) <= t1) { int pos = atomicAdd(&s_cnt[r0 + 8], 1); if (pos < 64)
                        g_cand[((size_t)(bm * 128 + r0 + 8)) * 64 + pos] = ((uint32_t)__half_as_ushort(h) << 16) | (uint32_t)(kk + 1); }
                }
            }
        }
    }
    __syncthreads();

    // ---- final: filter candidates with final threshold; unique -> exact; else rescore
    #pragma unroll 1
    for (int rr = 0; rr < 16; ++rr) {
        int lr = wid * 16 + rr;
        int row = bm * 128 + lr;
        int n = min(s_cnt[lr], 64);
        float thr = __half2float(__ushort_as_half((unsigned short)(s_rowmin[lr] >> 16))) + TAU;

        uint32_t c0 = 0xFFFFFFFFu, c1 = 0xFFFFFFFFu;
        bool v0 = false, v1 = false;
        if (lane < n) {
            uint32_t cd = g_cand[(size_t)row * 64 + lane];
            if (__half2float(__ushort_as_half((unsigned short)(cd >> 16))) <= thr) { v0 = true; c0 = cd; }
        }
        if (lane + 32 < n) {
            uint32_t cd = g_cand[(size_t)row * 64 + lane + 32];
            if (__half2float(__ushort_as_half((unsigned short)(cd >> 16))) <= thr) { v1 = true; c1 = cd; }
        }
        int vc = __popc(__ballot_sync(0xFFFFFFFFu, v0)) + __popc(__ballot_sync(0xFFFFFFFFu, v1));
        uint32_t mn = min(c0, c1);
        #pragma unroll
        for (int o = 16; o; o >>= 1) mn = min(mn, __shfl_xor_sync(0xFFFFFFFFu, mn, o));

        int kfin;
        if (vc == 1) {
            kfin = (int)(mn & 0xFFFFu);
        } else {
            float xs = xsq_s[lr];
            const float* xr = X + (size_t)row * D_;
            unsigned long long eb = ~0ull;
            for (int cc = 0; cc < n; ++cc) {
                uint32_t cd = g_cand[(size_t)row * 64 + cc];
                if (__half2float(__ushort_as_half((unsigned short)(cd >> 16))) > thr) continue;
                int k = (int)(cd & 0xFFFFu);
                const float* wr = g_Wtf + (size_t)k * D_;
                float s = 0.f;
                #pragma unroll
                for (int j = 0; j < 16; ++j)
                    s += xr[lane + j * 32] * wr[lane + j * 32];
                #pragma unroll
                for (int o = 16; o; o >>= 1) s += __shfl_xor_sync(0xFFFFFFFFu, s, o);
                float d2 = (xs - 2.0f * s) + g_wsq[k];
                float d  = __fsqrt_rn(fmaxf(d2, 0.0f));
                unsigned long long pk = ((unsigned long long)__float_as_uint(d) << 32) | (unsigned)k;
                eb = min(eb, pk);
            }
            kfin = (int)(eb & 0xFFFFFFFFull);
        }
        if (lane == 0) {
            g_assign[row] = kfin;
            out_am[row] = (float)kfin;
            atomicAdd(&g_counts[kfin], 1);
            atomicAdd(&g_bhist[kfin * C_ + keys[row]], 1);
        }
    }
}

// ---------------- cluster-size EMA + norm + prefix scan (shuffle, 2 barriers) ----------------
__global__ void k_stats(const float* __restrict__ cluster_size, float* __restrict__ out_ncs) {
    __shared__ float wsum[32];
    __shared__ int   wtot[32];
    __shared__ int   woff[32];
    __shared__ float s_n;
    int t = threadIdx.x, lane = t & 31, wid = t >> 5;

    int cnt = g_counts[t];
    float nidx = (cnt == 0) ? 1.0f : (float)cnt;
    float ncs = cluster_size[t] * GAM() + OMG() * nidx;
    out_ncs[t] = ncs;

    float s = ncs;
    #pragma unroll
    for (int o = 16; o; o >>= 1) s += __shfl_xor_sync(0xFFFFFFFFu, s, o);
    int sc = cnt;
    #pragma unroll
    for (int o = 1; o < 32; o <<= 1) {
        int v = __shfl_up_sync(0xFFFFFFFFu, sc, o);
        if (lane >= o) sc += v;
    }
    if (lane == 31) { wsum[wid] = s; wtot[wid] = sc; }
    __syncthreads();
    if (wid == 0) {
        float a = wsum[lane];
        float n = a;
        #pragma unroll
        for (int o = 16; o; o >>= 1) n += __shfl_xor_sync(0xFFFFFFFFu, n, o);
        if (lane == 0) s_n = n;
        int c = wtot[lane];
        int inc = c;
        #pragma unroll
        for (int o = 1; o < 32; o <<= 1) {
            int v = __shfl_up_sync(0xFFFFFFFFu, inc, o);
            if (lane >= o) inc += v;
        }
        woff[lane] = inc - c;
    }
    __syncthreads();
    float n = s_n;
    g_csnorm[t] = ((ncs + 1e-5f) / (n + KEPS())) * n;
    int excl = woff[wid] + (sc - cnt);
    g_offsets[t] = excl;
    g_cursor[t]  = excl;
}

// ---------------- counting-sort scatter ----------------
__global__ void k_scatter() {
    int b = blockIdx.x * blockDim.x + threadIdx.x;
    if (b >= B_) return;
    int k = g_assign[b];
    int pos = atomicAdd(&g_cursor[k], 1);
    g_order[pos] = b;
}

// ---------------- per-cluster embed_sum (coalesced gather, MLP=8) ----------------
__global__ void k_embed(const float* __restrict__ X) {
    int k = blockIdx.x;
    int d = threadIdx.x;
    int start = g_offsets[k], cnt = g_counts[k];
    const int* ord = g_order + start;
    float a0 = 0.f, a1 = 0.f, a2 = 0.f, a3 = 0.f;
    float a4 = 0.f, a5 = 0.f, a6 = 0.f, a7 = 0.f;
    int i = 0;
    for (; i + 8 <= cnt; i += 8) {
        a0 += X[(size_t)ord[i + 0] * D_ + d];
        a1 += X[(size_t)ord[i + 1] * D_ + d];
        a2 += X[(size_t)ord[i + 2] * D_ + d];
        a3 += X[(size_t)ord[i + 3] * D_ + d];
        a4 += X[(size_t)ord[i + 4] * D_ + d];
        a5 += X[(size_t)ord[i + 5] * D_ + d];
        a6 += X[(size_t)ord[i + 6] * D_ + d];
        a7 += X[(size_t)ord[i + 7] * D_ + d];
    }
    for (; i < cnt; ++i) a0 += X[(size_t)ord[i] * D_ + d];
    g_es[(size_t)k * D_ + d] = ((a0 + a1) + (a2 + a3)) + ((a4 + a5) + (a6 + a7));
}

// ---------------- embed_avg EMA + weight ----------------
__global__ void k_ema(const float* __restrict__ ea,
                      float* __restrict__ out_w, float* __restrict__ out_nea) {
    __shared__ float tile[32][33];
    int d0 = blockIdx.x * 32, k0 = blockIdx.y * 32;
    int tx = threadIdx.x, ty = threadIdx.y;
    tile[ty][tx] = g_es[(size_t)(k0 + ty) * D_ + d0 + tx];
    __syncthreads();
    int d = d0 + ty, k = k0 + tx;
    size_t idx = (size_t)d * K_ + k;
    float nea = ea[idx] * GAM() + OMG() * tile[tx][ty];
    out_nea[idx] = nea;
    out_w[idx]   = nea / g_csnorm[k];
}

// ---------------- hist EMA ----------------
__global__ void k_hist(const float* __restrict__ hist, float* __restrict__ out_h) {
    int i = blockIdx.x * blockDim.x + threadIdx.x;
    if (i < K_ * C_) out_h[i] = hist[i] * GAM() + OMG() * (float)g_bhist[i];
}

// ---------------- launch ----------------
extern "C" void kernel_launch(void* const* d_in, const int* in_sizes, int n_in,
                              void* d_out, int out_size) {
    const float* X    = (const float*)d_in[0];
    const int*   keys = (const int*)  d_in[1];
    const float* W    = (const float*)d_in[2];
    const float* cs   = (const float*)d_in[3];
    const float* ea   = (const float*)d_in[4];
    const float* hist = (const float*)d_in[5];

    float* out      = (float*)d_out;
    float* out_w    = out;
    float* out_ncs  = out + 524288;
    float* out_nea  = out + 525312;
    float* out_hist = out + 1049600;
    float* out_am   = out + 1152000;

    const int DSMEM = 65536 + 2 * BCHUNK;   // 102400
    cudaFuncSetAttribute(k_gemm_argmin, cudaFuncAttributeMaxDynamicSharedMemorySize, DSMEM);

    k_init<<<(K_ * C_ + 255) / 256, 256>>>();                  // launch 0
    k_wt<<<dim3(4, K_ / 32), dim3(32, 32)>>>(W);               // launch 1
    k_xconv<<<(B_ * 32) / 256, 256>>>(X);                      // launch 2
    k_gemm_argmin<<<B_ / 128, 256, DSMEM>>>(X, keys, out_am);  // launch 3 (profile slot)
    k_stats<<<1, K_>>>(cs, out_ncs);
    k_scatter<<<B_ / 256, 256>>>();
    k_embed<<<K_, D_>>>(X);
    k_ema<<<dim3(D_ / 32, K_ / 32), dim3(32, 32)>>>(ea, out_w, out_nea);
    k_hist<<<(K_ * C_ + 255) / 256, 256>>>(hist, out_hist);
}